// round 1
// baseline (speedup 1.0000x reference)
#include <cuda_runtime.h>
#include <math.h>

#ifndef M_PI
#define M_PI 3.14159265358979323846
#endif

// Problem constants
#define B_SZ   8
#define T_SZ   1024
#define DIMX   1024
#define DI     2048
#define NFFT   2048
#define ROWS   (B_SZ * T_SZ)   // 8192

// ----- device scratch (no runtime allocation allowed) -----
__device__ float  g_xproj[(size_t)ROWS * DI];  // 64 MB
__device__ float  g_gate [(size_t)ROWS * DI];  // 64 MB
__device__ float  g_pre  [(size_t)ROWS * DI];  // 64 MB
__device__ float  g_hseq [(size_t)ROWS * DI];  // 64 MB
__device__ float2 g_W  [NFFT];
__device__ float2 g_FCh[NFFT];
__device__ float2 g_FCx[NFFT];

__device__ __forceinline__ float2 cmulf(float2 a, float2 b){
    return make_float2(fmaf(a.x, b.x, -a.y * b.y), fmaf(a.x, b.y, a.y * b.x));
}

// ============================================================================
// 2048-point complex FFT, Stockham autosort, 5 radix-4 stages + 1 radix-2.
// 512 threads. Input in buf0 (caller synced). Output in buf0. Trailing sync.
// DIR = 0 forward (e^{-i}), DIR = 1 inverse (e^{+i}); no 1/N scaling here.
// W[k] = exp(-2*pi*i*k/2048).
// ============================================================================
template<int DIR>
__device__ __forceinline__ void fft2048(float2* buf0, float2* buf1,
                                        const float2* __restrict__ W, int tid)
{
    float2* X = buf0;
    float2* Y = buf1;
    int n = 2048, s = 1;
    #pragma unroll
    for (int st = 0; st < 5; ++st){
        const int m = n >> 2;
        const int p = tid / s;      // s is a power of two -> shift
        const int q = tid - p * s;
        const int base = q + s * p;
        float2 a = X[base];
        float2 b = X[base + s * m];
        float2 c = X[base + 2 * s * m];
        float2 d = X[base + 3 * s * m];
        float2 w1 = W[p * s], w2 = W[2 * p * s], w3 = W[3 * p * s];
        if (DIR){ w1.y = -w1.y; w2.y = -w2.y; w3.y = -w3.y; }
        float2 apc = make_float2(a.x + c.x, a.y + c.y);
        float2 amc = make_float2(a.x - c.x, a.y - c.y);
        float2 bpd = make_float2(b.x + d.x, b.y + d.y);
        float2 bmd = make_float2(b.x - d.x, b.y - d.y);
        float2 ib  = make_float2(-bmd.y, bmd.x);   // i * (b-d)
        float2 x0 = make_float2(apc.x + bpd.x, apc.y + bpd.y);
        float2 x2 = make_float2(apc.x - bpd.x, apc.y - bpd.y);
        float2 x1, x3;
        if (DIR == 0){
            x1 = make_float2(amc.x - ib.x, amc.y - ib.y);
            x3 = make_float2(amc.x + ib.x, amc.y + ib.y);
        } else {
            x1 = make_float2(amc.x + ib.x, amc.y + ib.y);
            x3 = make_float2(amc.x - ib.x, amc.y - ib.y);
        }
        const int ob = q + 4 * s * p;
        Y[ob]         = x0;
        Y[ob + s]     = cmulf(w1, x1);
        Y[ob + 2 * s] = cmulf(w2, x2);
        Y[ob + 3 * s] = cmulf(w3, x3);
        __syncthreads();
        float2* tmp = X; X = Y; Y = tmp;
        n >>= 2; s <<= 2;
    }
    // final radix-2 stage: n=2, s=1024, twiddle = 1
    #pragma unroll
    for (int r = 0; r < 2; ++r){
        const int q = tid + r * 512;
        float2 a = X[q], b = X[q + 1024];
        Y[q]        = make_float2(a.x + b.x, a.y + b.y);
        Y[q + 1024] = make_float2(a.x - b.x, a.y - b.y);
    }
    __syncthreads();   // result now in buf0 (== Y after odd # of swaps + final)
}

// ============================================================================
// Setup: twiddle table (double precision trig, one shot)
// ============================================================================
__global__ void twiddle_kernel(float2* __restrict__ W)
{
    int k = blockIdx.x * blockDim.x + threadIdx.x;
    if (k < NFFT){
        double a = -2.0 * M_PI * (double)k / (double)NFFT;
        W[k] = make_float2((float)cos(a), (float)sin(a));
    }
}

// ============================================================================
// Setup: FCh = fft(c_h)/N, FCx = fft(c_x)/N  via one packed complex FFT.
// z = c_h + i*c_x; FH = (Z[k]+conj(Z[-k]))/2; FX = (Z[k]-conj(Z[-k]))/(2i).
// ============================================================================
__global__ void spectra_kernel(const float* __restrict__ ch, const float* __restrict__ cx,
                               const float2* __restrict__ Wg,
                               float2* __restrict__ FCh, float2* __restrict__ FCx)
{
    extern __shared__ float2 sm[];
    float2* bufA = sm;
    float2* bufB = sm + 2048;
    float2* Wc   = sm + 4096;
    const int tid = threadIdx.x;
    for (int k = tid; k < NFFT; k += 512){
        Wc[k] = Wg[k];
        bufA[k] = make_float2(ch[k], cx[k]);
    }
    __syncthreads();
    fft2048<0>(bufA, bufB, Wc, tid);
    const float inv = 1.0f / (float)NFFT;
    for (int k = tid; k < NFFT; k += 512){
        float2 A  = bufA[k];
        float2 Zm = bufA[(NFFT - k) & (NFFT - 1)];
        float2 Bc = make_float2(Zm.x, -Zm.y);                // conj(Z[-k])
        float2 FH = make_float2(0.5f * (A.x + Bc.x), 0.5f * (A.y + Bc.y));
        float2 Dd = make_float2(A.x - Bc.x, A.y - Bc.y);
        float2 FX = make_float2(0.5f * Dd.y, -0.5f * Dd.x);  // Dd/(2i)
        FCh[k] = make_float2(FH.x * inv, FH.y * inv);
        FCx[k] = make_float2(FX.x * inv, FX.y * inv);
    }
}

// ============================================================================
// pre = circ_conv(c_x, x_proj) + b  — batch parallel, two rows per CTA packed
// as one complex sequence. grid = 4096, 512 threads, 64KB dyn smem.
// ============================================================================
__global__ void conv_pre_kernel(const float* __restrict__ xp, const float* __restrict__ bvec,
                                const float2* __restrict__ Wg, const float2* __restrict__ FCg,
                                float* __restrict__ pre)
{
    extern __shared__ float2 sm[];
    float2* bufA = sm;
    float2* bufB = sm + 2048;
    float2* Wc   = sm + 4096;
    float2* FC   = sm + 6144;
    const int tid = threadIdx.x;
    const size_t r0 = (size_t)blockIdx.x * 2;
    const float* x0 = xp + r0 * DI;
    const float* x1 = x0 + DI;
    for (int k = tid; k < NFFT; k += 512){
        Wc[k] = Wg[k];
        FC[k] = FCg[k];
        bufA[k] = make_float2(x0[k], x1[k]);
    }
    __syncthreads();
    fft2048<0>(bufA, bufB, Wc, tid);
    for (int k = tid; k < NFFT; k += 512) bufA[k] = cmulf(bufA[k], FC[k]);
    __syncthreads();
    fft2048<1>(bufA, bufB, Wc, tid);
    float* p0 = pre + r0 * DI;
    float* p1 = p0 + DI;
    for (int k = tid; k < NFFT; k += 512){
        const float bb = bvec[k];
        float2 v = bufA[k];
        p0[k] = v.x + bb;
        p1[k] = v.y + bb;
    }
}

// ============================================================================
// Sequential scan: h_t = tanh(circ_conv(c_h, h_{t-1}) + pre_t).
// One CTA per batch PAIR (z = h_b0 + i*h_b1). 4 CTAs, 512 threads, persistent.
// No inter-CTA sync needed: the 8 batch chains are independent.
// ============================================================================
__global__ void scan_kernel(const float* __restrict__ pre, float* __restrict__ hseq,
                            const float2* __restrict__ Wg, const float2* __restrict__ FCg,
                            const float* __restrict__ h0, float* __restrict__ hfinal)
{
    extern __shared__ float2 sm[];
    float2* bufA = sm;
    float2* bufB = sm + 2048;
    float2* Wc   = sm + 4096;
    float2* FC   = sm + 6144;
    const int tid = threadIdx.x;
    const int b0 = blockIdx.x * 2, b1 = b0 + 1;
    for (int k = tid; k < NFFT; k += 512){
        Wc[k] = Wg[k];
        FC[k] = FCg[k];
        bufA[k] = make_float2(h0[(size_t)b0 * DI + k], h0[(size_t)b1 * DI + k]);
    }
    __syncthreads();
    const float* pre0 = pre  + (size_t)b0 * T_SZ * DI;
    const float* pre1 = pre  + (size_t)b1 * T_SZ * DI;
    float*       hs0  = hseq + (size_t)b0 * T_SZ * DI;
    float*       hs1  = hseq + (size_t)b1 * T_SZ * DI;
    for (int t = 0; t < T_SZ; ++t){
        fft2048<0>(bufA, bufB, Wc, tid);
        #pragma unroll
        for (int k = tid; k < NFFT; k += 512) bufA[k] = cmulf(bufA[k], FC[k]);
        __syncthreads();
        fft2048<1>(bufA, bufB, Wc, tid);
        const size_t off = (size_t)t * DI;
        #pragma unroll
        for (int k = tid; k < NFFT; k += 512){
            float2 v = bufA[k];
            float hr = tanhf(v.x + pre0[off + k]);
            float hi = tanhf(v.y + pre1[off + k]);
            hs0[off + k] = hr;
            hs1[off + k] = hi;
            bufA[k] = make_float2(hr, hi);
        }
        __syncthreads();
    }
    if (hfinal){
        for (int k = tid; k < NFFT; k += 512){
            float2 v = bufA[k];
            hfinal[(size_t)b0 * DI + k] = v.x;
            hfinal[(size_t)b1 * DI + k] = v.y;
        }
    }
}

// ============================================================================
// SGEMM: C[M,N] = (A ⊙ A2)[M,K] * Bm[N,K]^T   (NT, both K-major, fp32)
// 128x128 tile, BK=16, 256 threads, 8x8 micro-tile.
// EPI==1: C = silu(C + bias[n])
// ============================================================================
template<int EPI>
__global__ void __launch_bounds__(256) gemm_nt(
    const float* __restrict__ A, const float* __restrict__ A2,
    const float* __restrict__ Bm, const float* __restrict__ bias,
    float* __restrict__ C, int M, int N, int K)
{
    __shared__ __align__(16) float As[16][128];
    __shared__ __align__(16) float Bs[16][128];
    const int tid = threadIdx.x;
    const int bm = blockIdx.y * 128, bn = blockIdx.x * 128;
    const int tx = tid & 15, ty = tid >> 4;
    float acc[8][8];
    #pragma unroll
    for (int i = 0; i < 8; ++i)
        #pragma unroll
        for (int j = 0; j < 8; ++j) acc[i][j] = 0.0f;

    const int lr = tid >> 2;
    const int lc = (tid & 3) << 2;

    for (int k0 = 0; k0 < K; k0 += 16){
        #pragma unroll
        for (int h = 0; h < 2; ++h){
            const int row = lr + h * 64;
            float4 av = *(const float4*)(A + (size_t)(bm + row) * K + k0 + lc);
            if (A2){
                float4 a2 = *(const float4*)(A2 + (size_t)(bm + row) * K + k0 + lc);
                av.x *= a2.x; av.y *= a2.y; av.z *= a2.z; av.w *= a2.w;
            }
            As[lc + 0][row] = av.x; As[lc + 1][row] = av.y;
            As[lc + 2][row] = av.z; As[lc + 3][row] = av.w;
            float4 bv = *(const float4*)(Bm + (size_t)(bn + row) * K + k0 + lc);
            Bs[lc + 0][row] = bv.x; Bs[lc + 1][row] = bv.y;
            Bs[lc + 2][row] = bv.z; Bs[lc + 3][row] = bv.w;
        }
        __syncthreads();
        #pragma unroll
        for (int kk = 0; kk < 16; ++kk){
            float4 a0 = *(const float4*)&As[kk][ty * 8];
            float4 a1 = *(const float4*)&As[kk][ty * 8 + 4];
            float4 b0 = *(const float4*)&Bs[kk][tx * 8];
            float4 b1 = *(const float4*)&Bs[kk][tx * 8 + 4];
            float ar[8] = {a0.x, a0.y, a0.z, a0.w, a1.x, a1.y, a1.z, a1.w};
            float br[8] = {b0.x, b0.y, b0.z, b0.w, b1.x, b1.y, b1.z, b1.w};
            #pragma unroll
            for (int i = 0; i < 8; ++i)
                #pragma unroll
                for (int j = 0; j < 8; ++j)
                    acc[i][j] = fmaf(ar[i], br[j], acc[i][j]);
        }
        __syncthreads();
    }

    #pragma unroll
    for (int i = 0; i < 8; ++i){
        const size_t row = (size_t)(bm + ty * 8 + i);
        #pragma unroll
        for (int j = 0; j < 8; j += 4){
            const int col = bn + tx * 8 + j;
            float4 v = make_float4(acc[i][j], acc[i][j + 1], acc[i][j + 2], acc[i][j + 3]);
            if (EPI == 1){
                v.x += bias[col];     v.y += bias[col + 1];
                v.z += bias[col + 2]; v.w += bias[col + 3];
                v.x = v.x / (1.0f + expf(-v.x));
                v.y = v.y / (1.0f + expf(-v.y));
                v.z = v.z / (1.0f + expf(-v.z));
                v.w = v.w / (1.0f + expf(-v.w));
            }
            *(float4*)(C + row * N + col) = v;
        }
    }
}

// ============================================================================
// Launch
// ============================================================================
extern "C" void kernel_launch(void* const* d_in, const int* in_sizes, int n_in,
                              void* d_out, int out_size)
{
    (void)in_sizes; (void)n_in;
    const float* x    = (const float*)d_in[0];
    const float* h0   = (const float*)d_in[1];
    const float* inw  = (const float*)d_in[2];
    const float* outw = (const float*)d_in[3];
    const float* ch   = (const float*)d_in[4];
    const float* cx   = (const float*)d_in[5];
    const float* bv   = (const float*)d_in[6];
    const float* wg   = (const float*)d_in[7];
    const float* bg   = (const float*)d_in[8];

    float* out = (float*)d_out;
    float* hfinal = (out_size >= (int)(ROWS * DIMX + B_SZ * DI))
                        ? out + (size_t)ROWS * DIMX : nullptr;

    float *p_xproj, *p_gate, *p_pre, *p_hseq;
    float2 *p_W, *p_FCh, *p_FCx;
    cudaGetSymbolAddress((void**)&p_xproj, g_xproj);
    cudaGetSymbolAddress((void**)&p_gate,  g_gate);
    cudaGetSymbolAddress((void**)&p_pre,   g_pre);
    cudaGetSymbolAddress((void**)&p_hseq,  g_hseq);
    cudaGetSymbolAddress((void**)&p_W,     g_W);
    cudaGetSymbolAddress((void**)&p_FCh,   g_FCh);
    cudaGetSymbolAddress((void**)&p_FCx,   g_FCx);

    cudaFuncSetAttribute(conv_pre_kernel, cudaFuncAttributeMaxDynamicSharedMemorySize, 65536);
    cudaFuncSetAttribute(scan_kernel,     cudaFuncAttributeMaxDynamicSharedMemorySize, 65536);

    // setup (cheap, deterministic, inside graph)
    twiddle_kernel<<<4, 512>>>(p_W);
    spectra_kernel<<<1, 512, 49152>>>(ch, cx, p_W, p_FCh, p_FCx);

    // GEMM1: x_proj = x @ in_proj_w^T   [8192,1024] x [2048,1024]^T
    gemm_nt<0><<<dim3(DI / 128, ROWS / 128), 256>>>(
        x, nullptr, inw, nullptr, p_xproj, ROWS, DI, DIMX);

    // pre = circ_conv(c_x, x_proj) + b
    conv_pre_kernel<<<ROWS / 2, 512, 65536>>>(p_xproj, bv, p_W, p_FCx, p_pre);

    // GEMM2: gate = silu(x_proj @ W_gate^T + b_gate)
    gemm_nt<1><<<dim3(DI / 128, ROWS / 128), 256>>>(
        p_xproj, nullptr, wg, bg, p_gate, ROWS, DI, DI);

    // sequential scan over T (4 persistent CTAs, batch pairs packed complex)
    scan_kernel<<<4, 512, 65536>>>(p_pre, p_hseq, p_W, p_FCh, h0, hfinal);

    // GEMM3: output = (h_seq * gate) @ out_proj_w^T
    gemm_nt<0><<<dim3(DIMX / 128, ROWS / 128), 256>>>(
        p_hseq, p_gate, outw, nullptr, out, ROWS, DIMX, DI);
}

// round 3
// speedup vs baseline: 1.4091x; 1.4091x over previous
#include <cuda_runtime.h>
#include <cuda_bf16.h>
#include <math.h>
#include <stdint.h>

#ifndef M_PI
#define M_PI 3.14159265358979323846
#endif

// Problem constants
#define B_SZ   8
#define T_SZ   1024
#define DIMX   1024
#define DI     2048
#define NFFT   2048
#define ROWS   (B_SZ * T_SZ)   // 8192

// ----- device scratch (no runtime allocation allowed) -----
__device__ float  g_gate [(size_t)ROWS * DI];
__device__ float  g_pre  [(size_t)ROWS * DI];
__device__ float  g_hseq [(size_t)ROWS * DI];
__device__ float2 g_W  [NFFT];
__device__ float2 g_FCh[NFFT];
__device__ float2 g_FCx[NFFT];

// bf16 split operands
__device__ __nv_bfloat16 g_xhi [(size_t)ROWS * DIMX];
__device__ __nv_bfloat16 g_xlo [(size_t)ROWS * DIMX];
__device__ __nv_bfloat16 g_xphi[(size_t)ROWS * DI];
__device__ __nv_bfloat16 g_xplo[(size_t)ROWS * DI];
__device__ __nv_bfloat16 g_clhi[(size_t)ROWS * DI];
__device__ __nv_bfloat16 g_cllo[(size_t)ROWS * DI];
__device__ __nv_bfloat16 g_iwhi[(size_t)DI * DIMX];
__device__ __nv_bfloat16 g_iwlo[(size_t)DI * DIMX];
__device__ __nv_bfloat16 g_wghi[(size_t)DI * DI];
__device__ __nv_bfloat16 g_wglo[(size_t)DI * DI];
__device__ __nv_bfloat16 g_owhi[(size_t)DIMX * DI];
__device__ __nv_bfloat16 g_owlo[(size_t)DIMX * DI];

__device__ __forceinline__ float2 cmulf(float2 a, float2 b){
    return make_float2(fmaf(a.x, b.x, -a.y * b.y), fmaf(a.x, b.y, a.y * b.x));
}

// ============================================================================
// PTX helpers (plain sm_103 — NO tcgen05, that needs the 'a' target)
// ============================================================================
__device__ __forceinline__ uint32_t smem_u32(const void* p){
    uint32_t a;
    asm("{ .reg .u64 t; cvta.to.shared.u64 t, %1; cvt.u32.u64 %0, t; }" : "=r"(a) : "l"(p));
    return a;
}
__device__ __forceinline__ void cpasync16(uint32_t dst, const void* src){
    asm volatile("cp.async.cg.shared.global [%0], [%1], 16;" :: "r"(dst), "l"(src));
}
#define CP_COMMIT()  asm volatile("cp.async.commit_group;" ::: "memory")
#define CP_WAIT(n)   asm volatile("cp.async.wait_group %0;" :: "n"(n) : "memory")

__device__ __forceinline__ void ldsm_x4(uint32_t* r, uint32_t addr){
    asm volatile("ldmatrix.sync.aligned.m8n8.x4.shared.b16 {%0,%1,%2,%3}, [%4];"
        : "=r"(r[0]), "=r"(r[1]), "=r"(r[2]), "=r"(r[3]) : "r"(addr));
}
__device__ __forceinline__ void mma16816(float* c, const uint32_t* a,
                                         uint32_t b0, uint32_t b1){
    asm volatile("mma.sync.aligned.m16n8k16.row.col.f32.bf16.bf16.f32 "
        "{%0,%1,%2,%3}, {%4,%5,%6,%7}, {%8,%9}, {%0,%1,%2,%3};"
        : "+f"(c[0]), "+f"(c[1]), "+f"(c[2]), "+f"(c[3])
        : "r"(a[0]), "r"(a[1]), "r"(a[2]), "r"(a[3]), "r"(b0), "r"(b1));
}

#define SWZ128(o) ((o) ^ (((o) >> 3) & 0x70))

// ============================================================================
// 2048-point complex FFT (Stockham, 5x radix-4 + radix-2), 512 threads.
// ============================================================================
template<int DIR>
__device__ __forceinline__ void fft2048(float2* buf0, float2* buf1,
                                        const float2* __restrict__ W, int tid)
{
    float2* X = buf0;
    float2* Y = buf1;
    int n = 2048, s = 1;
    #pragma unroll
    for (int st = 0; st < 5; ++st){
        const int m = n >> 2;
        const int p = tid / s;
        const int q = tid - p * s;
        const int base = q + s * p;
        float2 a = X[base];
        float2 b = X[base + s * m];
        float2 c = X[base + 2 * s * m];
        float2 d = X[base + 3 * s * m];
        float2 w1 = W[p * s], w2 = W[2 * p * s], w3 = W[3 * p * s];
        if (DIR){ w1.y = -w1.y; w2.y = -w2.y; w3.y = -w3.y; }
        float2 apc = make_float2(a.x + c.x, a.y + c.y);
        float2 amc = make_float2(a.x - c.x, a.y - c.y);
        float2 bpd = make_float2(b.x + d.x, b.y + d.y);
        float2 bmd = make_float2(b.x - d.x, b.y - d.y);
        float2 ib  = make_float2(-bmd.y, bmd.x);
        float2 x0 = make_float2(apc.x + bpd.x, apc.y + bpd.y);
        float2 x2 = make_float2(apc.x - bpd.x, apc.y - bpd.y);
        float2 x1, x3;
        if (DIR == 0){
            x1 = make_float2(amc.x - ib.x, amc.y - ib.y);
            x3 = make_float2(amc.x + ib.x, amc.y + ib.y);
        } else {
            x1 = make_float2(amc.x + ib.x, amc.y + ib.y);
            x3 = make_float2(amc.x - ib.x, amc.y - ib.y);
        }
        const int ob = q + 4 * s * p;
        Y[ob]         = x0;
        Y[ob + s]     = cmulf(w1, x1);
        Y[ob + 2 * s] = cmulf(w2, x2);
        Y[ob + 3 * s] = cmulf(w3, x3);
        __syncthreads();
        float2* tmp = X; X = Y; Y = tmp;
        n >>= 2; s <<= 2;
    }
    #pragma unroll
    for (int r = 0; r < 2; ++r){
        const int q = tid + r * 512;
        float2 a = X[q], b = X[q + 1024];
        Y[q]        = make_float2(a.x + b.x, a.y + b.y);
        Y[q + 1024] = make_float2(a.x - b.x, a.y - b.y);
    }
    __syncthreads();
}

// ============================================================================
__global__ void twiddle_kernel(float2* __restrict__ W)
{
    int k = blockIdx.x * blockDim.x + threadIdx.x;
    if (k < NFFT){
        double a = -2.0 * M_PI * (double)k / (double)NFFT;
        W[k] = make_float2((float)cos(a), (float)sin(a));
    }
}

__global__ void spectra_kernel(const float* __restrict__ ch, const float* __restrict__ cx,
                               const float2* __restrict__ Wg,
                               float2* __restrict__ FCh, float2* __restrict__ FCx)
{
    extern __shared__ float2 sm[];
    float2* bufA = sm;
    float2* bufB = sm + 2048;
    float2* Wc   = sm + 4096;
    const int tid = threadIdx.x;
    for (int k = tid; k < NFFT; k += 512){
        Wc[k] = Wg[k];
        bufA[k] = make_float2(ch[k], cx[k]);
    }
    __syncthreads();
    fft2048<0>(bufA, bufB, Wc, tid);
    const float inv = 1.0f / (float)NFFT;
    for (int k = tid; k < NFFT; k += 512){
        float2 A  = bufA[k];
        float2 Zm = bufA[(NFFT - k) & (NFFT - 1)];
        float2 Bc = make_float2(Zm.x, -Zm.y);
        float2 FH = make_float2(0.5f * (A.x + Bc.x), 0.5f * (A.y + Bc.y));
        float2 Dd = make_float2(A.x - Bc.x, A.y - Bc.y);
        float2 FX = make_float2(0.5f * Dd.y, -0.5f * Dd.x);
        FCh[k] = make_float2(FH.x * inv, FH.y * inv);
        FCx[k] = make_float2(FX.x * inv, FX.y * inv);
    }
}

// ============================================================================
// pre = circ_conv(c_x, x_proj) + b ; x_proj reconstructed from bf16 hi+lo.
// ============================================================================
__global__ void conv_pre_kernel(const __nv_bfloat16* __restrict__ xph,
                                const __nv_bfloat16* __restrict__ xpl,
                                const float* __restrict__ bvec,
                                const float2* __restrict__ Wg, const float2* __restrict__ FCg,
                                float* __restrict__ pre)
{
    extern __shared__ float2 sm[];
    float2* bufA = sm;
    float2* bufB = sm + 2048;
    float2* Wc   = sm + 4096;
    float2* FC   = sm + 6144;
    const int tid = threadIdx.x;
    const size_t r0 = (size_t)blockIdx.x * 2;
    const __nv_bfloat16* h0p = xph + r0 * DI;
    const __nv_bfloat16* l0p = xpl + r0 * DI;
    for (int k = tid; k < NFFT; k += 512){
        Wc[k] = Wg[k];
        FC[k] = FCg[k];
        float v0 = __bfloat162float(h0p[k]) + __bfloat162float(l0p[k]);
        float v1 = __bfloat162float(h0p[DI + k]) + __bfloat162float(l0p[DI + k]);
        bufA[k] = make_float2(v0, v1);
    }
    __syncthreads();
    fft2048<0>(bufA, bufB, Wc, tid);
    for (int k = tid; k < NFFT; k += 512) bufA[k] = cmulf(bufA[k], FC[k]);
    __syncthreads();
    fft2048<1>(bufA, bufB, Wc, tid);
    float* p0 = pre + r0 * DI;
    float* p1 = p0 + DI;
    for (int k = tid; k < NFFT; k += 512){
        const float bb = bvec[k];
        float2 v = bufA[k];
        p0[k] = v.x + bb;
        p1[k] = v.y + bb;
    }
}

// ============================================================================
// Sequential scan: 4 CTAs, batch pairs packed complex.
// ============================================================================
__global__ void scan_kernel(const float* __restrict__ pre, float* __restrict__ hseq,
                            const float2* __restrict__ Wg, const float2* __restrict__ FCg,
                            const float* __restrict__ h0, float* __restrict__ hfinal)
{
    extern __shared__ float2 sm[];
    float2* bufA = sm;
    float2* bufB = sm + 2048;
    float2* Wc   = sm + 4096;
    float2* FC   = sm + 6144;
    const int tid = threadIdx.x;
    const int b0 = blockIdx.x * 2, b1 = b0 + 1;
    for (int k = tid; k < NFFT; k += 512){
        Wc[k] = Wg[k];
        FC[k] = FCg[k];
        bufA[k] = make_float2(h0[(size_t)b0 * DI + k], h0[(size_t)b1 * DI + k]);
    }
    __syncthreads();
    const float* pre0 = pre  + (size_t)b0 * T_SZ * DI;
    const float* pre1 = pre  + (size_t)b1 * T_SZ * DI;
    float*       hs0  = hseq + (size_t)b0 * T_SZ * DI;
    float*       hs1  = hseq + (size_t)b1 * T_SZ * DI;
    for (int t = 0; t < T_SZ; ++t){
        fft2048<0>(bufA, bufB, Wc, tid);
        #pragma unroll
        for (int k = tid; k < NFFT; k += 512) bufA[k] = cmulf(bufA[k], FC[k]);
        __syncthreads();
        fft2048<1>(bufA, bufB, Wc, tid);
        const size_t off = (size_t)t * DI;
        #pragma unroll
        for (int k = tid; k < NFFT; k += 512){
            float2 v = bufA[k];
            float hr = tanhf(v.x + pre0[off + k]);
            float hi = tanhf(v.y + pre1[off + k]);
            hs0[off + k] = hr;
            hs1[off + k] = hi;
            bufA[k] = make_float2(hr, hi);
        }
        __syncthreads();
    }
    if (hfinal){
        for (int k = tid; k < NFFT; k += 512){
            float2 v = bufA[k];
            hfinal[(size_t)b0 * DI + k] = v.x;
            hfinal[(size_t)b1 * DI + k] = v.y;
        }
    }
}

// ============================================================================
// Elementwise split helpers
// ============================================================================
__global__ void split_kernel(const float* __restrict__ s,
                             __nv_bfloat16* __restrict__ hi, __nv_bfloat16* __restrict__ lo,
                             int n4)
{
    int i = blockIdx.x * blockDim.x + threadIdx.x;
    if (i >= n4) return;
    float4 v = ((const float4*)s)[i];
    __nv_bfloat16 h0 = __float2bfloat16(v.x), h1 = __float2bfloat16(v.y);
    __nv_bfloat16 h2 = __float2bfloat16(v.z), h3 = __float2bfloat16(v.w);
    __nv_bfloat16 l0 = __float2bfloat16(v.x - __bfloat162float(h0));
    __nv_bfloat16 l1 = __float2bfloat16(v.y - __bfloat162float(h1));
    __nv_bfloat16 l2 = __float2bfloat16(v.z - __bfloat162float(h2));
    __nv_bfloat16 l3 = __float2bfloat16(v.w - __bfloat162float(h3));
    ((__nv_bfloat162*)hi)[i * 2]     = __nv_bfloat162(h0, h1);
    ((__nv_bfloat162*)hi)[i * 2 + 1] = __nv_bfloat162(h2, h3);
    ((__nv_bfloat162*)lo)[i * 2]     = __nv_bfloat162(l0, l1);
    ((__nv_bfloat162*)lo)[i * 2 + 1] = __nv_bfloat162(l2, l3);
}

__global__ void cell_split_kernel(const float* __restrict__ a, const float* __restrict__ g,
                                  __nv_bfloat16* __restrict__ hi, __nv_bfloat16* __restrict__ lo,
                                  int n4)
{
    int i = blockIdx.x * blockDim.x + threadIdx.x;
    if (i >= n4) return;
    float4 va = ((const float4*)a)[i];
    float4 vg = ((const float4*)g)[i];
    float4 v = make_float4(va.x * vg.x, va.y * vg.y, va.z * vg.z, va.w * vg.w);
    __nv_bfloat16 h0 = __float2bfloat16(v.x), h1 = __float2bfloat16(v.y);
    __nv_bfloat16 h2 = __float2bfloat16(v.z), h3 = __float2bfloat16(v.w);
    __nv_bfloat16 l0 = __float2bfloat16(v.x - __bfloat162float(h0));
    __nv_bfloat16 l1 = __float2bfloat16(v.y - __bfloat162float(h1));
    __nv_bfloat16 l2 = __float2bfloat16(v.z - __bfloat162float(h2));
    __nv_bfloat16 l3 = __float2bfloat16(v.w - __bfloat162float(h3));
    ((__nv_bfloat162*)hi)[i * 2]     = __nv_bfloat162(h0, h1);
    ((__nv_bfloat162*)hi)[i * 2 + 1] = __nv_bfloat162(h2, h3);
    ((__nv_bfloat162*)lo)[i * 2]     = __nv_bfloat162(l0, l1);
    ((__nv_bfloat162*)lo)[i * 2 + 1] = __nv_bfloat162(l2, l3);
}

// ============================================================================
// mma.sync bf16 split GEMM: C[M,N] = A[M,K] * B[N,K]^T  (fp32 via 3-term split)
// CTA 128x128, K-chunk 64, cp.async double buffer, 8 warps (2x4), warp 64x32.
// EPI: 0 = fp32 store, 1 = silu(x+bias) fp32, 2 = bf16 hi/lo split store
// ============================================================================
#define KCH 64
#define STAGE_BYTES 65536   // 4 tiles x 16KB (Ahi, Alo, Bhi, Blo)

template<int EPI>
__global__ void __launch_bounds__(256, 1) gemm_mma(
    const __nv_bfloat16* __restrict__ Ahi, const __nv_bfloat16* __restrict__ Alo,
    const __nv_bfloat16* __restrict__ Bhi, const __nv_bfloat16* __restrict__ Blo,
    const float* __restrict__ bias,
    float* __restrict__ Cf,
    __nv_bfloat16* __restrict__ Chi, __nv_bfloat16* __restrict__ Clo,
    int K, int N)
{
    extern __shared__ char dsm[];
    const int tid  = threadIdx.x;
    const int wid  = tid >> 5;
    const int lane = tid & 31;
    const int wm = wid & 1;      // 0..1  (M)
    const int wn = wid >> 1;     // 0..3  (N)
    const int bm = blockIdx.y * 128;
    const int bn = blockIdx.x * 128;

    const uint32_t sbase = (smem_u32(dsm) + 1023u) & ~1023u;

    float acc[4][4][4];
    #pragma unroll
    for (int i = 0; i < 4; ++i)
        #pragma unroll
        for (int j = 0; j < 4; ++j)
            #pragma unroll
            for (int e = 0; e < 4; ++e) acc[i][j][e] = 0.0f;

    // ---- stage loader: 4 tiles of [128 rows][64 bf16] = 16KB each ----
    const int lrow = tid >> 3;       // 0..31
    const int lc   = tid & 7;        // 16B chunk 0..7
    auto load_stage = [&](int s, int k0){
        const uint32_t tA_hi = sbase + s * STAGE_BYTES;
        const uint32_t tA_lo = tA_hi + 16384;
        const uint32_t tB_hi = tA_hi + 32768;
        const uint32_t tB_lo = tA_hi + 49152;
        #pragma unroll
        for (int p = 0; p < 4; ++p){
            const int row = lrow + p * 32;
            const uint32_t sw = SWZ128((uint32_t)(row * 128 + lc * 16));
            const size_t ga = (size_t)(bm + row) * K + k0 + lc * 8;
            const size_t gb = (size_t)(bn + row) * K + k0 + lc * 8;
            cpasync16(tA_hi + sw, Ahi + ga);
            cpasync16(tA_lo + sw, Alo + ga);
            cpasync16(tB_hi + sw, Bhi + gb);
            cpasync16(tB_lo + sw, Blo + gb);
        }
        CP_COMMIT();
    };

    const int NIT = K / KCH;
    load_stage(0, 0);

    // per-lane ldmatrix address components (tile-local)
    const int lr8  = (lane & 7) + ((lane & 8) ? 8 : 0);   // row within 16-row tile
    const int lk16 = (lane & 16) ? 16 : 0;                // +16B for k8..15 tiles

    for (int it = 0; it < NIT; ++it){
        if (it + 1 < NIT){
            load_stage((it + 1) & 1, (it + 1) * KCH);
            CP_WAIT(1);
        } else {
            CP_WAIT(0);
        }
        __syncthreads();

        const uint32_t st   = sbase + (it & 1) * STAGE_BYTES;
        const uint32_t sAhi = st;
        const uint32_t sAlo = st + 16384;
        const uint32_t sBhi = st + 32768;
        const uint32_t sBlo = st + 49152;

        #pragma unroll
        for (int ks = 0; ks < 4; ++ks){
            uint32_t ah[4][4], al[4][4], bh[2][4], bl[2][4];
            #pragma unroll
            for (int i = 0; i < 4; ++i){
                const int r = wm * 64 + i * 16 + lr8;
                const uint32_t off = SWZ128((uint32_t)(r * 128 + ks * 32 + lk16));
                ldsm_x4(ah[i], sAhi + off);
                ldsm_x4(al[i], sAlo + off);
            }
            #pragma unroll
            for (int np = 0; np < 2; ++np){
                const int r = wn * 32 + np * 16 + lr8;
                const uint32_t off = SWZ128((uint32_t)(r * 128 + ks * 32 + lk16));
                ldsm_x4(bh[np], sBhi + off);
                ldsm_x4(bl[np], sBlo + off);
            }
            #pragma unroll
            for (int i = 0; i < 4; ++i){
                #pragma unroll
                for (int j = 0; j < 4; ++j){
                    const int np = j >> 1, sl = j & 1;
                    mma16816(acc[i][j], ah[i], bh[np][sl], bh[np][sl + 2]);
                    mma16816(acc[i][j], al[i], bh[np][sl], bh[np][sl + 2]);
                    mma16816(acc[i][j], ah[i], bl[np][sl], bl[np][sl + 2]);
                }
            }
        }
        __syncthreads();
    }

    // ---- epilogue ----
    const int qr = lane >> 2;        // 0..7
    const int qc = (lane & 3) * 2;   // 0,2,4,6
    #pragma unroll
    for (int i = 0; i < 4; ++i){
        #pragma unroll
        for (int j = 0; j < 4; ++j){
            const int col = bn + wn * 32 + j * 8 + qc;
            #pragma unroll
            for (int h = 0; h < 2; ++h){
                const int row = bm + wm * 64 + i * 16 + qr + h * 8;
                float v0 = acc[i][j][h * 2];
                float v1 = acc[i][j][h * 2 + 1];
                if (EPI == 1){
                    v0 += bias[col];
                    v1 += bias[col + 1];
                    v0 = v0 / (1.0f + expf(-v0));
                    v1 = v1 / (1.0f + expf(-v1));
                    *(float2*)(Cf + (size_t)row * N + col) = make_float2(v0, v1);
                } else if (EPI == 2){
                    __nv_bfloat16 h0 = __float2bfloat16(v0);
                    __nv_bfloat16 h1 = __float2bfloat16(v1);
                    __nv_bfloat16 l0 = __float2bfloat16(v0 - __bfloat162float(h0));
                    __nv_bfloat16 l1 = __float2bfloat16(v1 - __bfloat162float(h1));
                    *(__nv_bfloat162*)(Chi + (size_t)row * N + col) = __nv_bfloat162(h0, h1);
                    *(__nv_bfloat162*)(Clo + (size_t)row * N + col) = __nv_bfloat162(l0, l1);
                } else {
                    *(float2*)(Cf + (size_t)row * N + col) = make_float2(v0, v1);
                }
            }
        }
    }
}

// ============================================================================
// Launch
// ============================================================================
extern "C" void kernel_launch(void* const* d_in, const int* in_sizes, int n_in,
                              void* d_out, int out_size)
{
    (void)in_sizes; (void)n_in;
    const float* x    = (const float*)d_in[0];
    const float* h0   = (const float*)d_in[1];
    const float* inw  = (const float*)d_in[2];
    const float* outw = (const float*)d_in[3];
    const float* ch   = (const float*)d_in[4];
    const float* cx   = (const float*)d_in[5];
    const float* bv   = (const float*)d_in[6];
    const float* wg   = (const float*)d_in[7];
    const float* bg   = (const float*)d_in[8];

    float* out = (float*)d_out;
    float* hfinal = (out_size >= (int)(ROWS * DIMX + B_SZ * DI))
                        ? out + (size_t)ROWS * DIMX : nullptr;

    float *p_gate, *p_pre, *p_hseq;
    float2 *p_W, *p_FCh, *p_FCx;
    __nv_bfloat16 *p_xhi, *p_xlo, *p_xphi, *p_xplo, *p_clhi, *p_cllo;
    __nv_bfloat16 *p_iwhi, *p_iwlo, *p_wghi, *p_wglo, *p_owhi, *p_owlo;
    cudaGetSymbolAddress((void**)&p_gate,  g_gate);
    cudaGetSymbolAddress((void**)&p_pre,   g_pre);
    cudaGetSymbolAddress((void**)&p_hseq,  g_hseq);
    cudaGetSymbolAddress((void**)&p_W,     g_W);
    cudaGetSymbolAddress((void**)&p_FCh,   g_FCh);
    cudaGetSymbolAddress((void**)&p_FCx,   g_FCx);
    cudaGetSymbolAddress((void**)&p_xhi,   g_xhi);
    cudaGetSymbolAddress((void**)&p_xlo,   g_xlo);
    cudaGetSymbolAddress((void**)&p_xphi,  g_xphi);
    cudaGetSymbolAddress((void**)&p_xplo,  g_xplo);
    cudaGetSymbolAddress((void**)&p_clhi,  g_clhi);
    cudaGetSymbolAddress((void**)&p_cllo,  g_cllo);
    cudaGetSymbolAddress((void**)&p_iwhi,  g_iwhi);
    cudaGetSymbolAddress((void**)&p_iwlo,  g_iwlo);
    cudaGetSymbolAddress((void**)&p_wghi,  g_wghi);
    cudaGetSymbolAddress((void**)&p_wglo,  g_wglo);
    cudaGetSymbolAddress((void**)&p_owhi,  g_owhi);
    cudaGetSymbolAddress((void**)&p_owlo,  g_owlo);

    cudaFuncSetAttribute(conv_pre_kernel, cudaFuncAttributeMaxDynamicSharedMemorySize, 65536);
    cudaFuncSetAttribute(scan_kernel,     cudaFuncAttributeMaxDynamicSharedMemorySize, 65536);
    const int GSM = 2 * STAGE_BYTES + 1024;
    cudaFuncSetAttribute(gemm_mma<0>, cudaFuncAttributeMaxDynamicSharedMemorySize, GSM);
    cudaFuncSetAttribute(gemm_mma<1>, cudaFuncAttributeMaxDynamicSharedMemorySize, GSM);
    cudaFuncSetAttribute(gemm_mma<2>, cudaFuncAttributeMaxDynamicSharedMemorySize, GSM);

    // setup
    twiddle_kernel<<<4, 512>>>(p_W);
    spectra_kernel<<<1, 512, 49152>>>(ch, cx, p_W, p_FCh, p_FCx);

    // split inputs / weights to bf16 hi/lo
    split_kernel<<<(ROWS * DIMX / 4 + 255) / 256, 256>>>(x,    p_xhi,  p_xlo,  ROWS * DIMX / 4);
    split_kernel<<<(DI * DIMX   / 4 + 255) / 256, 256>>>(inw,  p_iwhi, p_iwlo, DI * DIMX / 4);
    split_kernel<<<(DI * DI     / 4 + 255) / 256, 256>>>(wg,   p_wghi, p_wglo, DI * DI / 4);
    split_kernel<<<(DIMX * DI   / 4 + 255) / 256, 256>>>(outw, p_owhi, p_owlo, DIMX * DI / 4);

    // GEMM1: x_proj = x @ in_proj_w^T  -> bf16 split  [8192,2048]
    gemm_mma<2><<<dim3(DI / 128, ROWS / 128), 256, GSM>>>(
        p_xhi, p_xlo, p_iwhi, p_iwlo, nullptr, nullptr, p_xphi, p_xplo, DIMX, DI);

    // pre = circ_conv(c_x, x_proj) + b
    conv_pre_kernel<<<ROWS / 2, 512, 65536>>>(p_xphi, p_xplo, bv, p_W, p_FCx, p_pre);

    // GEMM2: gate = silu(x_proj @ W_gate^T + b_gate)
    gemm_mma<1><<<dim3(DI / 128, ROWS / 128), 256, GSM>>>(
        p_xphi, p_xplo, p_wghi, p_wglo, bg, p_gate, nullptr, nullptr, DI, DI);

    // sequential scan
    scan_kernel<<<4, 512, 65536>>>(p_pre, p_hseq, p_W, p_FCh, h0, hfinal);

    // cell = hseq * gate -> bf16 split
    cell_split_kernel<<<(ROWS * DI / 4 + 255) / 256, 256>>>(
        p_hseq, p_gate, p_clhi, p_cllo, ROWS * DI / 4);

    // GEMM3: output = cell @ out_proj_w^T
    gemm_mma<0><<<dim3(DIMX / 128, ROWS / 128), 256, GSM>>>(
        p_clhi, p_cllo, p_owhi, p_owlo, nullptr, out, nullptr, nullptr, DI, DIMX);
}